// round 3
// baseline (speedup 1.0000x reference)
#include <cuda_runtime.h>

#define PPN 100
#define THREADS 512

__global__ __launch_bounds__(THREADS, 3) void pfn_kernel(
    const float* __restrict__ px, const float* __restrict__ py,
    const float* __restrict__ pz, const float* __restrict__ pi,
    const int*   __restrict__ nv,
    const float* __restrict__ xs, const float* __restrict__ ys,
    const float* __restrict__ W,  const float* __restrict__ gamma,
    const float* __restrict__ beta, const float* __restrict__ bmean,
    const float* __restrict__ bvar,
    float* __restrict__ out)
{
    __shared__ __align__(16) float sdata[6][PPN];
    // [0]=wx [1]=wy [2]=wz [3]=wi [4]=wxs [5]=wys [6..8]=mean-weights [9]=bias
    __shared__ float sW[10][32];
    __shared__ float ssum[3];
    __shared__ float pmax[32][33];   // [point-group][channel]
    __shared__ float part[8][33];    // first-stage max partials
    __shared__ float bmax[32];

    const int p   = blockIdx.x;
    const int tid = threadIdx.x;
    const size_t off = (size_t)p * PPN;

    // ---- stage inputs first: 6 arrays x 25 float4 ----
    if (tid < 150) {
        const int a = tid / 25, j = tid % 25;
        const float* src = (a == 0) ? px : (a == 1) ? py : (a == 2) ? pz
                         : (a == 3) ? pi : (a == 4) ? xs : ys;
        ((float4*)&sdata[a][0])[j] = ((const float4*)(src + off))[j];
    }

    // ---- fold BN + feature algebra into weights (one warp, overlaps loads) ----
    if (tid >= 480) {
        const int u = tid - 480;
        const float* Wr = W + u * 9;
        float w0 = Wr[0], w1 = Wr[1], w2 = Wr[2], w3 = Wr[3];
        float w4 = Wr[4], w5 = Wr[5], w6 = Wr[6], w7 = Wr[7], w8 = Wr[8];
        float s = rsqrtf(bvar[u] + 1e-3f) * gamma[u];
        sW[0][u] = (w0 + w4 + w7) * s;
        sW[1][u] = (w1 + w5 + w8) * s;
        sW[2][u] = (w2 + w6) * s;
        sW[3][u] = w3 * s;
        sW[4][u] = -w7 * s;
        sW[5][u] = -w8 * s;
        sW[6][u] = w4 * s;
        sW[7][u] = w5 * s;
        sW[8][u] = w6 * s;
        sW[9][u] = beta[u] - bmean[u] * s;
    }
    __syncthreads();

    // ---- points_mean: sum over ALL N slots (reference semantics) ----
    const int wid = tid >> 5, lane = tid & 31;
    if (wid < 3) {
        const float* a = sdata[wid];
        float s = 0.f;
        #pragma unroll
        for (int n = lane; n < PPN; n += 32) s += a[n];
        #pragma unroll
        for (int o = 16; o; o >>= 1) s += __shfl_down_sync(0xffffffffu, s, o);
        if (lane == 0) ssum[wid] = s;
    }
    __syncthreads();

    const int   nvp = nv[p];
    const float fnv = (float)nvp;
    const float mx = ssum[0] / fnv, my = ssum[1] / fnv, mz = ssum[2] / fnv;

    const int q  = tid & 15;   // channel pair: channels {2q, 2q+1}
    const int ng = tid >> 4;   // point group in [0,32)

    float wx[2], wy[2], wz[2], wi[2], wxs[2], wys[2], b[2], K[2];
    #pragma unroll
    for (int j = 0; j < 2; j++) {
        const int u = q * 2 + j;
        wx[j]  = sW[0][u]; wy[j]  = sW[1][u]; wz[j] = sW[2][u];
        wi[j]  = sW[3][u]; wxs[j] = sW[4][u]; wys[j] = sW[5][u];
        b[j]   = sW[9][u];
        K[j]   = -(mx * sW[6][u] + my * sW[7][u] + mz * sW[8][u]);
    }

    float vmax[2] = {-1e30f, -1e30f};
    float2* out2 = (float2*)(out + off * 64);   // 32 float2 per point

    #pragma unroll
    for (int base = 0; base < PPN; base += 32) {
        const int n = base + ng;
        if (n < PPN) {
            const float x  = sdata[0][n], y  = sdata[1][n], z = sdata[2][n];
            const float it = sdata[3][n], xv = sdata[4][n], yv = sdata[5][n];
            const float m  = (n < nvp) ? 1.f : 0.f;

            float r[2];
            #pragma unroll
            for (int j = 0; j < 2; j++) {
                float acc = K[j];
                acc = fmaf(x,  wx[j],  acc);
                acc = fmaf(y,  wy[j],  acc);
                acc = fmaf(z,  wz[j],  acc);
                acc = fmaf(it, wi[j],  acc);
                acc = fmaf(xv, wxs[j], acc);
                acc = fmaf(yv, wys[j], acc);
                r[j] = fmaxf(fmaf(m, acc, b[j]), 0.f);
                vmax[j] = fmaxf(vmax[j], r[j]);
            }
            float2 v; v.x = r[0]; v.y = r[1];
            __stcs(&out2[(size_t)n * 32 + q], v);           // channels [0,32)
        }
    }

    pmax[ng][q * 2 + 0] = vmax[0];
    pmax[ng][q * 2 + 1] = vmax[1];
    __syncthreads();

    // two-stage max reduce: 256 threads -> 8 partials -> 32 finals
    if (tid < 256) {
        const int ch = tid & 31, g = tid >> 5;   // g in [0,8): rows 4g..4g+3
        float v = pmax[g * 4][ch];
        v = fmaxf(v, pmax[g * 4 + 1][ch]);
        v = fmaxf(v, pmax[g * 4 + 2][ch]);
        v = fmaxf(v, pmax[g * 4 + 3][ch]);
        part[g][ch] = v;
    }
    __syncthreads();
    if (tid < 32) {
        float v = part[0][tid];
        #pragma unroll
        for (int g = 1; g < 8; g++) v = fmaxf(v, part[g][tid]);
        bmax[tid] = v;
    }
    __syncthreads();

    float2 bc;
    bc.x = bmax[q * 2 + 0]; bc.y = bmax[q * 2 + 1];
    #pragma unroll
    for (int base = 0; base < PPN; base += 32) {
        const int n = base + ng;
        if (n < PPN) __stcs(&out2[(size_t)n * 32 + 16 + q], bc);  // channels [32,64)
    }
}

extern "C" void kernel_launch(void* const* d_in, const int* in_sizes, int n_in,
                              void* d_out, int out_size)
{
    const float* px    = (const float*)d_in[0];
    const float* py    = (const float*)d_in[1];
    const float* pz    = (const float*)d_in[2];
    const float* pi    = (const float*)d_in[3];
    const int*   nv    = (const int*  )d_in[4];
    const float* xs    = (const float*)d_in[5];
    const float* ys    = (const float*)d_in[6];
    // d_in[7] = mask : derivable from num_voxels, not read
    const float* W     = (const float*)d_in[8];
    const float* gamma = (const float*)d_in[9];
    const float* beta  = (const float*)d_in[10];
    const float* bmean = (const float*)d_in[11];
    const float* bvar  = (const float*)d_in[12];

    const int P = in_sizes[4];
    pfn_kernel<<<P, THREADS>>>(px, py, pz, pi, nv, xs, ys,
                               W, gamma, beta, bmean, bvar, (float*)d_out);
}

// round 4
// speedup vs baseline: 1.3888x; 1.3888x over previous
#include <cuda_runtime.h>
#include <cstdint>

#define PPN 100
#define THREADS 256

__device__ __forceinline__ uint32_t smem_u32(const void* p) {
    uint32_t a;
    asm("{ .reg .u64 t; cvta.to.shared.u64 t, %1; cvt.u32.u64 %0, t; }" : "=r"(a) : "l"(p));
    return a;
}
__device__ __forceinline__ void cp_async16(uint32_t saddr, const void* g) {
    asm volatile("cp.async.cg.shared.global [%0], [%1], 16;" :: "r"(saddr), "l"(g));
}
__device__ __forceinline__ void cp_commit() { asm volatile("cp.async.commit_group;"); }
__device__ __forceinline__ void cp_wait0()  { asm volatile("cp.async.wait_group 0;"); }

__global__ __launch_bounds__(THREADS, 4) void pfn_kernel(
    const float* __restrict__ px, const float* __restrict__ py,
    const float* __restrict__ pz, const float* __restrict__ pi,
    const int*   __restrict__ nv,
    const float* __restrict__ xs, const float* __restrict__ ys,
    const float* __restrict__ W,  const float* __restrict__ gamma,
    const float* __restrict__ beta, const float* __restrict__ bmean,
    const float* __restrict__ bvar,
    float* __restrict__ out, int P)
{
    __shared__ __align__(16) float sdata[2][6][PPN];
    // [0]=wx [1]=wy [2]=wz [3]=wi [4]=wxs [5]=wys [6..8]=mean-weights [9]=bias
    __shared__ float sW[10][32];
    __shared__ float ssum[3];
    __shared__ float pmax[32][33];
    __shared__ float bmax[32];

    const int tid  = threadIdx.x;
    const int wid  = tid >> 5, lane = tid & 31;
    const int stride = gridDim.x;

    // ---- fold BN + feature algebra into weights (once per CTA) ----
    if (tid < 32) {
        const float* Wr = W + tid * 9;
        float w0 = Wr[0], w1 = Wr[1], w2 = Wr[2], w3 = Wr[3];
        float w4 = Wr[4], w5 = Wr[5], w6 = Wr[6], w7 = Wr[7], w8 = Wr[8];
        float s = rsqrtf(bvar[tid] + 1e-3f) * gamma[tid];
        sW[0][tid] = (w0 + w4 + w7) * s;
        sW[1][tid] = (w1 + w5 + w8) * s;
        sW[2][tid] = (w2 + w6) * s;
        sW[3][tid] = w3 * s;
        sW[4][tid] = -w7 * s;
        sW[5][tid] = -w8 * s;
        sW[6][tid] = w4 * s;
        sW[7][tid] = w5 * s;
        sW[8][tid] = w6 * s;
        sW[9][tid] = beta[tid] - bmean[tid] * s;
    }

    // per-thread staging role: 150 threads move one float4 each
    const int a = tid / 25, j = tid % 25;     // a in [0,6) valid when tid<150
    const float* src = (a == 0) ? px : (a == 1) ? py : (a == 2) ? pz
                     : (a == 3) ? pi : (a == 4) ? xs : ys;

    const int pid0 = blockIdx.x;

    // ---- preload first pillar into buffer 0 ----
    if (pid0 < P && tid < 150) {
        cp_async16(smem_u32(&sdata[0][a][j * 4]), src + (size_t)pid0 * PPN + j * 4);
        cp_commit();
    }
    int nvp = (pid0 < P) ? __ldg(nv + pid0) : 1;
    cp_wait0();
    __syncthreads();

    const int q  = tid & 7;    // channel quad
    const int ng = tid >> 3;   // point group

    // static (per-CTA) weight micro-tile
    float wx[4], wy[4], wz[4], wi[4], wxs[4], wys[4], b[4], km[3][4];
    #pragma unroll
    for (int t = 0; t < 4; t++) {
        const int u = q * 4 + t;
        wx[t]  = sW[0][u]; wy[t]  = sW[1][u]; wz[t] = sW[2][u];
        wi[t]  = sW[3][u]; wxs[t] = sW[4][u]; wys[t] = sW[5][u];
        km[0][t] = sW[6][u]; km[1][t] = sW[7][u]; km[2][t] = sW[8][u];
        b[t]   = sW[9][u];
    }

    int buf = 0;
    for (int pp = pid0; pp < P; pp += stride) {
        const int nxt = pp + stride;

        // prefetch next pillar into the other buffer (async, overlaps everything)
        if (nxt < P && tid < 150) {
            cp_async16(smem_u32(&sdata[buf ^ 1][a][j * 4]),
                       src + (size_t)nxt * PPN + j * 4);
            cp_commit();
        }
        const int nv_next = (nxt < P) ? __ldg(nv + nxt) : 1;

        // ---- points_mean over ALL N slots ----
        if (wid < 3) {
            const float* arr = sdata[buf][wid];
            float s = 0.f;
            #pragma unroll
            for (int n = lane; n < PPN; n += 32) s += arr[n];
            #pragma unroll
            for (int o = 16; o; o >>= 1) s += __shfl_down_sync(0xffffffffu, s, o);
            if (lane == 0) ssum[wid] = s;
        }
        __syncthreads();

        const float fnv = (float)nvp;
        const float mx = ssum[0] / fnv, my = ssum[1] / fnv, mz = ssum[2] / fnv;

        float K[4];
        #pragma unroll
        for (int t = 0; t < 4; t++)
            K[t] = -(mx * km[0][t] + my * km[1][t] + mz * km[2][t]);

        float vmax[4] = {-1e30f, -1e30f, -1e30f, -1e30f};
        float4* out4 = (float4*)(out + (size_t)pp * PPN * 64);

        #pragma unroll
        for (int base = 0; base < PPN; base += 32) {
            const int n = base + ng;
            if (n < PPN) {
                const float x  = sdata[buf][0][n], y  = sdata[buf][1][n];
                const float z  = sdata[buf][2][n], it = sdata[buf][3][n];
                const float xv = sdata[buf][4][n], yv = sdata[buf][5][n];
                const float m  = (n < nvp) ? 1.f : 0.f;

                float r[4];
                #pragma unroll
                for (int t = 0; t < 4; t++) {
                    float acc = K[t];
                    acc = fmaf(x,  wx[t],  acc);
                    acc = fmaf(y,  wy[t],  acc);
                    acc = fmaf(z,  wz[t],  acc);
                    acc = fmaf(it, wi[t],  acc);
                    acc = fmaf(xv, wxs[t], acc);
                    acc = fmaf(yv, wys[t], acc);
                    r[t] = fmaxf(fmaf(m, acc, b[t]), 0.f);
                    vmax[t] = fmaxf(vmax[t], r[t]);
                }
                float4 v; v.x = r[0]; v.y = r[1]; v.z = r[2]; v.w = r[3];
                __stcs(&out4[(size_t)n * 16 + q], v);        // channels [0,32)
            }
        }

        #pragma unroll
        for (int t = 0; t < 4; t++) pmax[ng][q * 4 + t] = vmax[t];
        __syncthreads();

        if (tid < 32) {
            float v = pmax[0][tid];
            #pragma unroll
            for (int r2 = 1; r2 < 32; r2++) v = fmaxf(v, pmax[r2][tid]);
            bmax[tid] = v;
        }
        __syncthreads();

        float4 bc;
        bc.x = bmax[q * 4 + 0]; bc.y = bmax[q * 4 + 1];
        bc.z = bmax[q * 4 + 2]; bc.w = bmax[q * 4 + 3];
        #pragma unroll
        for (int base = 0; base < PPN; base += 32) {
            const int n = base + ng;
            if (n < PPN) __stcs(&out4[(size_t)n * 16 + 8 + q], bc);  // [32,64)
        }

        nvp = nv_next;
        cp_wait0();          // next buffer fully staged
        __syncthreads();
        buf ^= 1;
    }
}

extern "C" void kernel_launch(void* const* d_in, const int* in_sizes, int n_in,
                              void* d_out, int out_size)
{
    const float* px    = (const float*)d_in[0];
    const float* py    = (const float*)d_in[1];
    const float* pz    = (const float*)d_in[2];
    const float* pi    = (const float*)d_in[3];
    const int*   nv    = (const int*  )d_in[4];
    const float* xs    = (const float*)d_in[5];
    const float* ys    = (const float*)d_in[6];
    // d_in[7] = mask : derivable from num_voxels, not read
    const float* W     = (const float*)d_in[8];
    const float* gamma = (const float*)d_in[9];
    const float* beta  = (const float*)d_in[10];
    const float* bmean = (const float*)d_in[11];
    const float* bvar  = (const float*)d_in[12];

    const int P = in_sizes[4];
    int ctas = 148 * 4;
    if (ctas > P) ctas = P;
    pfn_kernel<<<ctas, THREADS>>>(px, py, pz, pi, nv, xs, ys,
                                  W, gamma, beta, bmean, bvar, (float*)d_out, P);
}